// round 5
// baseline (speedup 1.0000x reference)
#include <cuda_runtime.h>

// ---------------------------------------------------------------------------
// 16-qubit statevector sim, batch 64, batch-pairs packed into f32x2 lanes.
//
//  * Per layer: Pass B = wires 0..3 (bits 15..12), Pass A = wires 4..15.
//  * CNOT chain == Gray-code permutation psi'[b] = psi[b ^ (b>>1)], fused
//    into the next Pass B gather and into the final Pauli-Z sign pattern.
//  * Two batch elements per 64-bit lane pair; gates via fma.rn.f32x2.
//  * Grid sized to 256 CTAs (2 chunks per CTA) -> exactly one wave at
//    2 CTAs/SM on 148 SMs; gates computed per-CTA in smem (no prep kernel).
// ---------------------------------------------------------------------------

typedef unsigned long long ull;

#define DIM   65536
#define BATCH 64
#define NPAIR 32

__device__ ull g_bufr0[NPAIR * DIM];   // 16 MB each
__device__ ull g_bufi0[NPAIR * DIM];
__device__ ull g_bufr1[NPAIR * DIM];
__device__ ull g_bufi1[NPAIR * DIM];
__device__ float2 g_partial[NPAIR * 8];

// ---------------- f32x2 helpers ----------------
__device__ __forceinline__ ull dup2(float v) {
    ull r; asm("mov.b64 %0, {%1, %1};" : "=l"(r) : "f"(v)); return r;
}
__device__ __forceinline__ ull pk2(float a, float b) {
    ull r; asm("mov.b64 %0, {%1, %2};" : "=l"(r) : "f"(a), "f"(b)); return r;
}
__device__ __forceinline__ float2 up2(ull v) {
    float2 r; asm("mov.b64 {%0, %1}, %2;" : "=f"(r.x), "=f"(r.y) : "l"(v)); return r;
}
__device__ __forceinline__ ull ffma2(ull a, ull b, ull c) {
    ull d; asm("fma.rn.f32x2 %0, %1, %2, %3;" : "=l"(d) : "l"(a), "l"(b), "l"(c)); return d;
}
__device__ __forceinline__ ull fmul2(ull a, ull b) {
    ull d; asm("mul.rn.f32x2 %0, %1, %2;" : "=l"(d) : "l"(a), "l"(b)); return d;
}

// ---------------------------------------------------------------------------
// Gate matrix U = Rz Ry Rx; only first row (u00, u01) needed:
// u10 = (-u01r, u01i), u11 = (u00r, -u00i).
// ---------------------------------------------------------------------------
__device__ __forceinline__ float4 make_gate(const float* __restrict__ vp,
                                            int layer, int wire) {
    int g = layer * 16 + wire;
    float tx = vp[g * 6 + 0], ty = vp[g * 6 + 1], tz = vp[g * 6 + 2];
    float cx, sx, cy, sy, cz, sz;
    sincosf(tx * 0.5f, &sx, &cx);
    sincosf(ty * 0.5f, &sy, &cy);
    sincosf(tz * 0.5f, &sz, &cz);
    float cycx = cy * cx, sysx = sy * sx, sycx = sy * cx, cysx = cy * sx;
    float4 u;
    u.x =  cz * cycx + sz * sysx;   // u00r
    u.y =  cz * sysx - sz * cycx;   // u00i
    u.z = -cz * sycx - sz * cysx;   // u01r
    u.w =  sz * sycx - cz * cysx;   // u01i
    return u;
}

struct GateP { ull c00r, c00i, n00i, c01r, n01r, c01i, n01i; };

__device__ __forceinline__ GateP mk_gateP(float4 u0) {
    GateP g;
    g.c00r = dup2(u0.x); g.c00i = dup2(u0.y); g.n00i = dup2(-u0.y);
    g.c01r = dup2(u0.z); g.n01r = dup2(-u0.z);
    g.c01i = dup2(u0.w); g.n01i = dup2(-u0.w);
    return g;
}

__device__ __forceinline__ void cgateP(ull& a0r, ull& a0i, ull& a1r, ull& a1i,
                                       const GateP& g) {
    ull p0r = ffma2(g.c00r, a0r, ffma2(g.n00i, a0i, ffma2(g.c01r, a1r, fmul2(g.n01i, a1i))));
    ull p0i = ffma2(g.c00r, a0i, ffma2(g.c00i, a0r, ffma2(g.c01r, a1i, fmul2(g.c01i, a1r))));
    ull p1r = ffma2(g.n01r, a0r, ffma2(g.n01i, a0i, ffma2(g.c00r, a1r, fmul2(g.c00i, a1i))));
    ull p1i = ffma2(g.n01r, a0i, ffma2(g.c01i, a0r, ffma2(g.c00r, a1i, fmul2(g.n00i, a1r))));
    a0r = p0r; a0i = p0i; a1r = p1r; a1i = p1i;
}

template <int BIT>
__device__ __forceinline__ void apply_localP(ull vr[16], ull vi[16], const GateP& g) {
    constexpr int S = 1 << BIT;
#pragma unroll
    for (int base = 0; base < 16; base += 2 * S)
#pragma unroll
        for (int off = 0; off < S; off++)
            cgateP(vr[base + off], vi[base + off], vr[base + off + S], vi[base + off + S], g);
}

// ---------------------------------------------------------------------------
// Pass B: wires 0..3 (bits 15..12). Thread owns 16 packed amps at stride 4096.
// 256 CTAs; each CTA processes j-chunks c and c+8 for its pair.
// mode 0: planar inputs -> buf0.  mode 1: buf0 --Gray--> buf1.
// mode 2: buf1 --Gray--> buf0.
// ---------------------------------------------------------------------------
__global__ void __launch_bounds__(256, 2) pass_high(int layer, int mode,
                                                    const float* __restrict__ sr,
                                                    const float* __restrict__ si,
                                                    const float* __restrict__ vp) {
    __shared__ float4 sg[4];
    unsigned t = threadIdx.x;
    if (t < 4) sg[t] = make_gate(vp, layer, (int)t);
    __syncthreads();

    unsigned pair = blockIdx.x >> 3;
    unsigned c = blockIdx.x & 7u;
    unsigned base = pair << 16;

    const ull* __restrict__ srcr = (mode == 1) ? g_bufr0 : g_bufr1;
    const ull* __restrict__ srci = (mode == 1) ? g_bufi0 : g_bufi1;
    ull* __restrict__ dr = (mode == 1) ? g_bufr1 : g_bufr0;
    ull* __restrict__ di = (mode == 1) ? g_bufi1 : g_bufi0;

#pragma unroll 1
    for (int half = 0; half < 2; half++) {
        unsigned j = ((c | (half ? 8u : 0u)) << 8) | t;   // low 12 bits

        ull vr[16], vi[16];
        if (mode == 0) {
            unsigned b0 = (pair << 1) << 16, b1 = ((pair << 1) | 1u) << 16;
#pragma unroll
            for (int h = 0; h < 16; h++) {
                unsigned idx = ((unsigned)h << 12) + j;
                vr[h] = pk2(sr[b0 + idx], sr[b1 + idx]);
                vi[h] = pk2(si[b0 + idx], si[b1 + idx]);
            }
        } else {
            unsigned jg = j ^ (j >> 1);
#pragma unroll
            for (int h = 0; h < 16; h++) {
                unsigned hg = (unsigned)h ^ ((unsigned)h >> 1);
                unsigned lo = jg ^ ((h & 1u) << 11);
                unsigned idx = base + (hg << 12) + lo;
                vr[h] = srcr[idx];
                vi[h] = srci[idx];
            }
        }

        { GateP g = mk_gateP(sg[0]); apply_localP<3>(vr, vi, g); }
        { GateP g = mk_gateP(sg[1]); apply_localP<2>(vr, vi, g); }
        { GateP g = mk_gateP(sg[2]); apply_localP<1>(vr, vi, g); }
        { GateP g = mk_gateP(sg[3]); apply_localP<0>(vr, vi, g); }

#pragma unroll
        for (int h = 0; h < 16; h++) {
            unsigned idx = base + ((unsigned)h << 12) + j;
            dr[idx] = vr[h];
            di[idx] = vi[h];
        }
    }
}

// XOR swizzle over 8B words
__device__ __forceinline__ unsigned sw(unsigned a) { return a ^ ((a >> 4) & 15u); }

// ---------------------------------------------------------------------------
// Pass A: wires 4..15 (bits 11..0), in-place per 4096-amp chunk.
// 256 CTAs; each CTA processes H-chunks H and H+8 for its pair.
// final_pass=1: fold layer-3 Gray into Pauli-Z signs, accumulate head dot.
// ---------------------------------------------------------------------------
__global__ void __launch_bounds__(256, 2) pass_low(int layer, int which, int final_pass,
                                                   const float* __restrict__ hw,
                                                   const float* __restrict__ vp) {
    extern __shared__ ull smem_dyn[];
    ull* shr = smem_dyn;
    ull* shi = smem_dyn + 4096;
    __shared__ float4 sg[12];
    __shared__ float2 red[8];

    unsigned t = threadIdx.x;
    if (t < 12) sg[t] = make_gate(vp, layer, 4 + (int)t);
    __syncthreads();

    ull* __restrict__ bufr = which ? g_bufr1 : g_bufr0;
    ull* __restrict__ bufi = which ? g_bufi1 : g_bufi0;

    unsigned pair = blockIdx.x >> 3;
    unsigned Hlo = blockIdx.x & 7u;
    unsigned hi = (t >> 4) << 8, lo = t & 15u;

    ull acc = dup2(0.f);

#pragma unroll 1
    for (int half = 0; half < 2; half++) {
        unsigned H = Hlo | (half ? 8u : 0u);
        unsigned cb = (pair << 16) | (H << 12);

        ull vr[16], vi[16];

        // Round 1: thread owns bits 11..8 (a = k<<8 | t)
#pragma unroll
        for (int k = 0; k < 16; k++) {
            unsigned idx = cb + ((unsigned)k << 8) + t;
            vr[k] = bufr[idx];
            vi[k] = bufi[idx];
        }
        { GateP g = mk_gateP(sg[3]); apply_localP<0>(vr, vi, g); }   // wire 7, bit 8
        { GateP g = mk_gateP(sg[2]); apply_localP<1>(vr, vi, g); }   // wire 6, bit 9
        { GateP g = mk_gateP(sg[1]); apply_localP<2>(vr, vi, g); }   // wire 5, bit 10
        { GateP g = mk_gateP(sg[0]); apply_localP<3>(vr, vi, g); }   // wire 4, bit 11

        // Exchange -> Round 2: thread owns bits 7..4
#pragma unroll
        for (int k = 0; k < 16; k++) {
            unsigned a = sw(((unsigned)k << 8) | t);
            shr[a] = vr[k]; shi[a] = vi[k];
        }
        __syncthreads();
#pragma unroll
        for (int k = 0; k < 16; k++) {
            unsigned a = sw(hi | ((unsigned)k << 4) | lo);
            vr[k] = shr[a]; vi[k] = shi[a];
        }
        { GateP g = mk_gateP(sg[7]); apply_localP<0>(vr, vi, g); }   // wire 11, bit 4
        { GateP g = mk_gateP(sg[6]); apply_localP<1>(vr, vi, g); }   // wire 10, bit 5
        { GateP g = mk_gateP(sg[5]); apply_localP<2>(vr, vi, g); }   // wire 9,  bit 6
        { GateP g = mk_gateP(sg[4]); apply_localP<3>(vr, vi, g); }   // wire 8,  bit 7
        __syncthreads();

        // Exchange -> Round 3: thread owns bits 3..0
#pragma unroll
        for (int k = 0; k < 16; k++) {
            unsigned a = sw(hi | ((unsigned)k << 4) | lo);
            shr[a] = vr[k]; shi[a] = vi[k];
        }
        __syncthreads();
#pragma unroll
        for (int k = 0; k < 16; k++) {
            unsigned a = sw((t << 4) | (unsigned)k);
            vr[k] = shr[a]; vi[k] = shi[a];
        }
        { GateP g = mk_gateP(sg[11]); apply_localP<0>(vr, vi, g); }  // wire 15, bit 0
        { GateP g = mk_gateP(sg[10]); apply_localP<1>(vr, vi, g); }  // wire 14, bit 1
        { GateP g = mk_gateP(sg[ 9]); apply_localP<2>(vr, vi, g); }  // wire 13, bit 2
        { GateP g = mk_gateP(sg[ 8]); apply_localP<3>(vr, vi, g); }  // wire 12, bit 3

        if (!final_pass) {
            // vectorized in-place store (a = t<<4 | k)
#pragma unroll
            for (int k = 0; k < 16; k += 2) {
                unsigned idx = cb + (t << 4) + (unsigned)k;
                *reinterpret_cast<ulonglong2*>(&bufr[idx]) = make_ulonglong2(vr[k], vr[k + 1]);
                *reinterpret_cast<ulonglong2*>(&bufi[idx]) = make_ulonglong2(vi[k], vi[k + 1]);
            }
        } else {
            // psi_final[b] = psi_rot[gray(b)]; bit at position (15-q) of b
            // equals parity(s >> (15-q)).  coeff(s) = sum_q ±hw[q].
            float w[16];
#pragma unroll
            for (int q = 0; q < 16; q++) w[q] = hw[q];

            unsigned shidx = (H << 8) | t;   // bits 15..4 of s
            int run = 0; float c0 = 0.f;
#pragma unroll
            for (int q = 0; q <= 11; q++) {
                run ^= (int)((shidx >> (11 - q)) & 1u);
                c0 += run ? -w[q] : w[q];
            }
#pragma unroll
            for (int k = 0; k < 16; k++) {
                int r = run; float cc = c0;
                r ^= (k >> 3) & 1; cc += r ? -w[12] : w[12];
                r ^= (k >> 2) & 1; cc += r ? -w[13] : w[13];
                r ^= (k >> 1) & 1; cc += r ? -w[14] : w[14];
                r ^=  k       & 1; cc += r ? -w[15] : w[15];
                ull prob = ffma2(vr[k], vr[k], fmul2(vi[k], vi[k]));
                acc = ffma2(dup2(cc), prob, acc);
            }
        }
        __syncthreads();   // smem reuse / next half
    }

    if (final_pass) {
        float2 a = up2(acc);
#pragma unroll
        for (int o = 16; o > 0; o >>= 1) {
            a.x += __shfl_down_sync(0xffffffffu, a.x, o);
            a.y += __shfl_down_sync(0xffffffffu, a.y, o);
        }
        if ((t & 31u) == 0) red[t >> 5] = a;
        __syncthreads();
        if (t == 0) {
            float2 s = make_float2(0.f, 0.f);
#pragma unroll
            for (int i = 0; i < 8; i++) { s.x += red[i].x; s.y += red[i].y; }
            g_partial[(pair << 3) | Hlo] = s;
        }
    }
}

__global__ void head_kernel(float* __restrict__ out, const float* __restrict__ hb) {
    int b = threadIdx.x;
    if (b < BATCH) {
        float s = hb[0];
        int pair = b >> 1;
#pragma unroll
        for (int c = 0; c < 8; c++) {
            float2 p = g_partial[(pair << 3) | c];
            s += (b & 1) ? p.y : p.x;
        }
        out[b] = s;
    }
}

// ---------------------------------------------------------------------------
extern "C" void kernel_launch(void* const* d_in, const int* in_sizes, int n_in,
                              void* d_out, int out_size) {
    const float* sr = (const float*)d_in[0];
    const float* si = (const float*)d_in[1];
    const float* vp = (const float*)d_in[2];
    const float* hw = (const float*)d_in[3];
    const float* hb = (const float*)d_in[4];
    float* out = (float*)d_out;
    (void)in_sizes; (void)n_in; (void)out_size;

    cudaFuncSetAttribute(pass_low, cudaFuncAttributeMaxDynamicSharedMemorySize, 65536);

    // layer 0
    pass_high<<<256, 256>>>(0, 0, sr, si, vp);             // inputs -> buf0
    pass_low <<<256, 256, 65536>>>(0, 0, 0, hw, vp);       // buf0 in place
    // layer 1 (Gray of layer 0 fused into gather)
    pass_high<<<256, 256>>>(1, 1, nullptr, nullptr, vp);   // buf0 -> buf1
    pass_low <<<256, 256, 65536>>>(1, 1, 0, hw, vp);       // buf1 in place
    // layer 2
    pass_high<<<256, 256>>>(2, 2, nullptr, nullptr, vp);   // buf1 -> buf0
    pass_low <<<256, 256, 65536>>>(2, 0, 1, hw, vp);       // buf0 -> partials

    head_kernel<<<1, 64>>>(out, hb);
}